// round 1
// baseline (speedup 1.0000x reference)
#include <cuda_runtime.h>
#include <math.h>

// Problem constants
#define BB 2
#define NN 1024
#define CSD 384
#define HH 12
#define CC 16
#define PQN 4
#define PVN 8
#define NPAD 1026        // N + 2*PAD
#define PROW 512         // num_pool
#define TT 1538          // NPAD + PROW
#define HC 192           // H*C
#define HPQ3 144         // H*PQ*3
#define HPV3 288         // H*PV*3
#define OCW 576          // HC + HPV3 + H*PV

#define C1 0.176776695f       // w_l * (1/sqrt(C)) = sqrt(0.5)*0.25
#define WC_HALF 0.117851130f  // w_c/2 = sqrt(2/(9*PQ))/2

// Scratch (device globals; no allocation allowed)
__device__ float g_s_all[BB*TT*CSD];
__device__ float g_t_all[BB*TT*3];
__device__ float g_r_all[BB*TT*9];
__device__ float g_k  [BB*TT*HC];
__device__ float g_v  [BB*TT*HC];
__device__ float g_kp [BB*TT*HPQ3];   // local points -> global (in place)
__device__ float g_vp [BB*TT*HPV3];   // local points -> global (in place)
__device__ float g_sk [BB*TT*HH];
__device__ float g_q  [BB*PROW*HC];
__device__ float g_qp [BB*PROW*HPQ3]; // local -> global (in place)
__device__ float g_o  [BB*PROW*HC];
__device__ float g_opg[BB*PROW*HPV3];
__device__ float g_oc [BB*PROW*OCW];
__device__ float g_su [BB*PROW*CSD];

__device__ __forceinline__ int clampsrc(int e) {
    int v = e - 1;
    return v < 0 ? 0 : (v > NN - 1 ? NN - 1 : v);
}

// ---------------------------------------------------------------------------
// Pooling prep: s_all
// ---------------------------------------------------------------------------
__global__ void prep_s_kernel(const float* __restrict__ s) {
    int idx = blockIdx.x * blockDim.x + threadIdx.x;
    if (idx >= BB * TT * CSD) return;
    int c = idx % CSD;
    int bt = idx / CSD;
    int t = bt % TT;
    int b = bt / TT;
    float val;
    if (t < NPAD) {
        val = s[(b * NN + clampsrc(t)) * CSD + c];
    } else {
        int p = t - NPAD;
        val = (s[(b * NN + clampsrc(2 * p    )) * CSD + c]
             + s[(b * NN + clampsrc(2 * p + 1)) * CSD + c]
             + s[(b * NN + clampsrc(2 * p + 2)) * CSD + c]) * (1.f / 3.f);
    }
    g_s_all[idx] = val;
}

// t_all (3 comps) + r_all (9 comps)
__global__ void prep_tr_kernel(const float* __restrict__ trans,
                               const float* __restrict__ rots) {
    int idx = blockIdx.x * blockDim.x + threadIdx.x;
    if (idx >= BB * TT * 12) return;
    int d = idx % 12;
    int bt = idx / 12;
    int t = bt % TT;
    int b = bt / TT;
    if (d < 3) {
        float val;
        if (t < NPAD) {
            val = trans[(b * NN + clampsrc(t)) * 3 + d];
        } else {
            int p = t - NPAD;
            val = (trans[(b * NN + clampsrc(2 * p    )) * 3 + d]
                 + trans[(b * NN + clampsrc(2 * p + 1)) * 3 + d]
                 + trans[(b * NN + clampsrc(2 * p + 2)) * 3 + d]) * (1.f / 3.f);
        }
        g_t_all[(b * TT + t) * 3 + d] = val;
    } else {
        int r = d - 3;
        float val;
        if (t < NPAD) {
            val = rots[(b * NN + clampsrc(t)) * 9 + r];
        } else {
            int p = t - NPAD;
            val = (rots[(b * NN + clampsrc(2 * p    )) * 9 + r]
                 + rots[(b * NN + clampsrc(2 * p + 1)) * 9 + r]
                 + rots[(b * NN + clampsrc(2 * p + 2)) * 9 + r]) * (1.f / 3.f);
        }
        g_r_all[(b * TT + t) * 9 + r] = val;
    }
}

// ---------------------------------------------------------------------------
// Generic SGEMM: C[M,N] = A[M,K] @ B[K,N], row-major, fp32.
// BM=BN=64, BK=16, 256 threads, 4x4 per thread.
// ---------------------------------------------------------------------------
#define GBM 64
#define GBN 64
#define GBK 16
__global__ void sgemm_kernel(const float* __restrict__ A,
                             const float* __restrict__ Bm,
                             float* __restrict__ Cm,
                             int M, int Nn, int K) {
    __shared__ float As[GBK][GBM];
    __shared__ float Bs[GBK][GBN];
    int tid = threadIdx.x;
    int tx = tid % 16, ty = tid / 16;
    int row0 = blockIdx.y * GBM;
    int col0 = blockIdx.x * GBN;
    float acc[4][4];
#pragma unroll
    for (int i = 0; i < 4; i++)
#pragma unroll
        for (int j = 0; j < 4; j++) acc[i][j] = 0.f;

    for (int k0 = 0; k0 < K; k0 += GBK) {
#pragma unroll
        for (int x = 0; x < (GBM * GBK) / 256; x++) {
            int li = tid + x * 256;
            int m = li / GBK, kk = li % GBK;
            int gm = row0 + m;
            As[kk][m] = (gm < M) ? A[(long)gm * K + k0 + kk] : 0.f;
        }
#pragma unroll
        for (int x = 0; x < (GBK * GBN) / 256; x++) {
            int li = tid + x * 256;
            int kk = li / GBN, n = li % GBN;
            int gn = col0 + n;
            Bs[kk][n] = (gn < Nn) ? Bm[(long)(k0 + kk) * Nn + gn] : 0.f;
        }
        __syncthreads();
#pragma unroll
        for (int kk = 0; kk < GBK; kk++) {
            float a[4], bvals[4];
#pragma unroll
            for (int i = 0; i < 4; i++) a[i] = As[kk][ty * 4 + i];
#pragma unroll
            for (int j = 0; j < 4; j++) bvals[j] = Bs[kk][tx * 4 + j];
#pragma unroll
            for (int i = 0; i < 4; i++)
#pragma unroll
                for (int j = 0; j < 4; j++) acc[i][j] += a[i] * bvals[j];
        }
        __syncthreads();
    }
#pragma unroll
    for (int i = 0; i < 4; i++) {
        int gm = row0 + ty * 4 + i;
        if (gm >= M) continue;
#pragma unroll
        for (int j = 0; j < 4; j++) {
            int gn = col0 + tx * 4 + j;
            if (gn < Nn) Cm[(long)gm * Nn + gn] = acc[i][j];
        }
    }
}

// ---------------------------------------------------------------------------
// Transform K/V points to global frame, compute sk. One thread per (b,t,h).
// ---------------------------------------------------------------------------
__global__ void transform_kv_kernel() {
    int idx = blockIdx.x * blockDim.x + threadIdx.x;
    if (idx >= BB * TT * HH) return;
    int h = idx % HH;
    int rt = idx / HH;  // b*TT + t
    float R[9], tr[3];
#pragma unroll
    for (int r = 0; r < 9; r++) R[r] = g_r_all[rt * 9 + r];
#pragma unroll
    for (int r = 0; r < 3; r++) tr[r] = g_t_all[rt * 3 + r];

    float sk = 0.f;
    int kb = rt * HPQ3 + h * PQN * 3;
#pragma unroll
    for (int p = 0; p < PQN; p++) {
        float lx = g_kp[kb + p * 3 + 0];
        float ly = g_kp[kb + p * 3 + 1];
        float lz = g_kp[kb + p * 3 + 2];
        float gx = R[0] * lx + R[1] * ly + R[2] * lz + tr[0];
        float gy = R[3] * lx + R[4] * ly + R[5] * lz + tr[1];
        float gz = R[6] * lx + R[7] * ly + R[8] * lz + tr[2];
        g_kp[kb + p * 3 + 0] = gx;
        g_kp[kb + p * 3 + 1] = gy;
        g_kp[kb + p * 3 + 2] = gz;
        sk += gx * gx + gy * gy + gz * gz;
    }
    g_sk[rt * HH + h] = sk;

    int vb = rt * HPV3 + h * PVN * 3;
#pragma unroll
    for (int p = 0; p < PVN; p++) {
        float lx = g_vp[vb + p * 3 + 0];
        float ly = g_vp[vb + p * 3 + 1];
        float lz = g_vp[vb + p * 3 + 2];
        float gx = R[0] * lx + R[1] * ly + R[2] * lz + tr[0];
        float gy = R[3] * lx + R[4] * ly + R[5] * lz + tr[1];
        float gz = R[6] * lx + R[7] * ly + R[8] * lz + tr[2];
        g_vp[vb + p * 3 + 0] = gx;
        g_vp[vb + p * 3 + 1] = gy;
        g_vp[vb + p * 3 + 2] = gz;
    }
}

__global__ void transform_q_kernel() {
    int idx = blockIdx.x * blockDim.x + threadIdx.x;
    if (idx >= BB * PROW * HH) return;
    int h = idx % HH;
    int row = idx / HH;             // b*PROW + i
    int b = row / PROW, i = row % PROW;
    int ridx = b * TT + NPAD + i;
    float R[9], tr[3];
#pragma unroll
    for (int r = 0; r < 9; r++) R[r] = g_r_all[ridx * 9 + r];
#pragma unroll
    for (int r = 0; r < 3; r++) tr[r] = g_t_all[ridx * 3 + r];
    int qb = row * HPQ3 + h * PQN * 3;
#pragma unroll
    for (int p = 0; p < PQN; p++) {
        float lx = g_qp[qb + p * 3 + 0];
        float ly = g_qp[qb + p * 3 + 1];
        float lz = g_qp[qb + p * 3 + 2];
        float gx = R[0] * lx + R[1] * ly + R[2] * lz + tr[0];
        float gy = R[3] * lx + R[4] * ly + R[5] * lz + tr[1];
        float gz = R[6] * lx + R[7] * ly + R[8] * lz + tr[2];
        g_qp[qb + p * 3 + 0] = gx;
        g_qp[qb + p * 3 + 1] = gy;
        g_qp[qb + p * 3 + 2] = gz;
    }
}

// ---------------------------------------------------------------------------
// Attention: one thread per query row, blocks of 64 rows, one (b,h) per
// blockIdx.x. Online (flash) softmax over j-tiles of 32 staged in smem.
// ---------------------------------------------------------------------------
#define TJ 32
#define ATH 64
__global__ void attn_kernel(const float* __restrict__ gamma) {
    int bh = blockIdx.x;                 // 0..B*H-1
    int b = bh / HH, h = bh % HH;
    int i = blockIdx.y * ATH + threadIdx.x;   // 0..PROW-1
    int tid = threadIdx.x;

    __shared__ float sk_s[TJ];
    __shared__ float k_s[TJ][CC];
    __shared__ float kg_s[TJ][PQN * 3];
    __shared__ float v_s[TJ][CC];
    __shared__ float vg_s[TJ][PVN * 3];

    int qrow = b * PROW + i;
    float q[CC], qg[PQN * 3];
#pragma unroll
    for (int c = 0; c < CC; c++) q[c] = g_q[qrow * HC + h * CC + c];
#pragma unroll
    for (int x = 0; x < PQN * 3; x++) qg[x] = g_qp[qrow * HPQ3 + h * PQN * 3 + x];
    float sq = 0.f;
#pragma unroll
    for (int x = 0; x < PQN * 3; x++) sq += qg[x] * qg[x];

    float gm = gamma[h];
    float gcoef = logf(1.f + __expf(gm)) * WC_HALF;  // softplus(gamma)*w_c/2

    float mrun = -1e30f, lrun = 0.f;
    float ao[CC], ag[PVN * 3];
#pragma unroll
    for (int c = 0; c < CC; c++) ao[c] = 0.f;
#pragma unroll
    for (int x = 0; x < PVN * 3; x++) ag[x] = 0.f;

    for (int j0 = 0; j0 < TT; j0 += TJ) {
        __syncthreads();
        for (int x = tid; x < TJ * CC; x += ATH) {
            int j = x / CC, c = x % CC;
            int jj = j0 + j;
            k_s[j][c] = (jj < TT) ? g_k[(b * TT + jj) * HC + h * CC + c] : 0.f;
        }
        for (int x = tid; x < TJ * CC; x += ATH) {
            int j = x / CC, c = x % CC;
            int jj = j0 + j;
            v_s[j][c] = (jj < TT) ? g_v[(b * TT + jj) * HC + h * CC + c] : 0.f;
        }
        for (int x = tid; x < TJ * PQN * 3; x += ATH) {
            int j = x / (PQN * 3), c = x % (PQN * 3);
            int jj = j0 + j;
            kg_s[j][c] = (jj < TT) ? g_kp[(b * TT + jj) * HPQ3 + h * PQN * 3 + c] : 0.f;
        }
        for (int x = tid; x < TJ * PVN * 3; x += ATH) {
            int j = x / (PVN * 3), c = x % (PVN * 3);
            int jj = j0 + j;
            vg_s[j][c] = (jj < TT) ? g_vp[(b * TT + jj) * HPV3 + h * PVN * 3 + c] : 0.f;
        }
        for (int x = tid; x < TJ; x += ATH) {
            int jj = j0 + x;
            sk_s[x] = (jj < TT) ? g_sk[(b * TT + jj) * HH + h] : 0.f;
        }
        __syncthreads();

        int nv = TT - j0;
        if (nv > TJ) nv = TJ;

        float logit[TJ];
        float tmax = -1e30f;
#pragma unroll
        for (int jj = 0; jj < TJ; jj++) {
            float qk = 0.f;
#pragma unroll
            for (int c = 0; c < CC; c++) qk += q[c] * k_s[jj][c];
            float dt = 0.f;
#pragma unroll
            for (int x = 0; x < PQN * 3; x++) dt += qg[x] * kg_s[jj][x];
            float d2 = sq + sk_s[jj] - 2.f * dt;
            float lg = C1 * qk - gcoef * d2;
            logit[jj] = (jj < nv) ? lg : -1e30f;
            tmax = fmaxf(tmax, logit[jj]);
        }
        float mn = fmaxf(mrun, tmax);
        float corr = __expf(mrun - mn);
        lrun *= corr;
#pragma unroll
        for (int c = 0; c < CC; c++) ao[c] *= corr;
#pragma unroll
        for (int x = 0; x < PVN * 3; x++) ag[x] *= corr;
#pragma unroll
        for (int jj = 0; jj < TJ; jj++) {
            float e = __expf(logit[jj] - mn);
            lrun += e;
#pragma unroll
            for (int c = 0; c < CC; c++) ao[c] += e * v_s[jj][c];
#pragma unroll
            for (int x = 0; x < PVN * 3; x++) ag[x] += e * vg_s[jj][x];
        }
        mrun = mn;
    }
    float inv = 1.f / lrun;
#pragma unroll
    for (int c = 0; c < CC; c++) g_o[qrow * HC + h * CC + c] = ao[c] * inv;
#pragma unroll
    for (int x = 0; x < PVN * 3; x++)
        g_opg[qrow * HPV3 + h * PVN * 3 + x] = ag[x] * inv;
}

// ---------------------------------------------------------------------------
// Build oc rows: [o | opl | norms]. One thread per (b,i,h).
// ---------------------------------------------------------------------------
__global__ void build_oc_kernel() {
    int idx = blockIdx.x * blockDim.x + threadIdx.x;
    if (idx >= BB * PROW * HH) return;
    int h = idx % HH;
    int row = idx / HH;
    int b = row / PROW, i = row % PROW;
    int ridx = b * TT + NPAD + i;
    float R[9], tr[3];
#pragma unroll
    for (int r = 0; r < 9; r++) R[r] = g_r_all[ridx * 9 + r];
#pragma unroll
    for (int r = 0; r < 3; r++) tr[r] = g_t_all[ridx * 3 + r];

#pragma unroll
    for (int c = 0; c < CC; c++)
        g_oc[row * OCW + h * CC + c] = g_o[row * HC + h * CC + c];

#pragma unroll
    for (int p = 0; p < PVN; p++) {
        float gx = g_opg[row * HPV3 + h * PVN * 3 + p * 3 + 0] - tr[0];
        float gy = g_opg[row * HPV3 + h * PVN * 3 + p * 3 + 1] - tr[1];
        float gz = g_opg[row * HPV3 + h * PVN * 3 + p * 3 + 2] - tr[2];
        // R^T @ diff
        float lx = R[0] * gx + R[3] * gy + R[6] * gz;
        float ly = R[1] * gx + R[4] * gy + R[7] * gz;
        float lz = R[2] * gx + R[5] * gy + R[8] * gz;
        g_oc[row * OCW + HC + h * PVN * 3 + p * 3 + 0] = lx;
        g_oc[row * OCW + HC + h * PVN * 3 + p * 3 + 1] = ly;
        g_oc[row * OCW + HC + h * PVN * 3 + p * 3 + 2] = lz;
        g_oc[row * OCW + HC + HPV3 + h * PVN + p] =
            sqrtf(lx * lx + ly * ly + lz * lz + 1e-8f);
    }
}

// ---------------------------------------------------------------------------
// Finalize: upd = su@wupd + b, quaternion rotation update, write outputs.
// out layout: [t_new flat (B*PROW*3) | r_new flat (B*PROW*9)]
// ---------------------------------------------------------------------------
__global__ void finalize_kernel(const float* __restrict__ wupd,
                                const float* __restrict__ bupd,
                                float* __restrict__ out) {
    int row = blockIdx.x * blockDim.x + threadIdx.x;
    if (row >= BB * PROW) return;
    int b = row / PROW, i = row % PROW;
    int ridx = b * TT + NPAD + i;

    float u[6];
#pragma unroll
    for (int j = 0; j < 6; j++) u[j] = bupd[j];
    const float* su = g_su + (long)row * CSD;
    for (int k = 0; k < CSD; k++) {
        float sv = su[k];
#pragma unroll
        for (int j = 0; j < 6; j++) u[j] += sv * wupd[k * 6 + j];
    }

    float bq = u[0], cq = u[1], dq = u[2];
    float ninv = rsqrtf(1.f + bq * bq + cq * cq + dq * dq);
    float w = ninv, x = bq * ninv, y = cq * ninv, z = dq * ninv;
    float Ru[9];
    Ru[0] = 1.f - 2.f * (y * y + z * z); Ru[1] = 2.f * (x * y - w * z); Ru[2] = 2.f * (x * z + w * y);
    Ru[3] = 2.f * (x * y + w * z); Ru[4] = 1.f - 2.f * (x * x + z * z); Ru[5] = 2.f * (y * z - w * x);
    Ru[6] = 2.f * (x * z - w * y); Ru[7] = 2.f * (y * z + w * x); Ru[8] = 1.f - 2.f * (x * x + y * y);

    float R[9];
#pragma unroll
    for (int r = 0; r < 9; r++) R[r] = g_r_all[ridx * 9 + r];

    float Rn[9];
#pragma unroll
    for (int r = 0; r < 3; r++)
#pragma unroll
        for (int c = 0; c < 3; c++) {
            float acc = 0.f;
#pragma unroll
            for (int k = 0; k < 3; k++) acc += R[r * 3 + k] * Ru[k * 3 + c];
            Rn[r * 3 + c] = acc;
        }

    float tnx = R[0] * u[3] + R[1] * u[4] + R[2] * u[5] + g_t_all[ridx * 3 + 0];
    float tny = R[3] * u[3] + R[4] * u[4] + R[5] * u[5] + g_t_all[ridx * 3 + 1];
    float tnz = R[6] * u[3] + R[7] * u[4] + R[8] * u[5] + g_t_all[ridx * 3 + 2];

    out[row * 3 + 0] = tnx;
    out[row * 3 + 1] = tny;
    out[row * 3 + 2] = tnz;
    float* rout = out + BB * PROW * 3;
#pragma unroll
    for (int r = 0; r < 9; r++) rout[row * 9 + r] = Rn[r];
}

// ---------------------------------------------------------------------------
extern "C" void kernel_launch(void* const* d_in, const int* in_sizes, int n_in,
                              void* d_out, int out_size) {
    const float* trans = (const float*)d_in[0];
    const float* rots  = (const float*)d_in[1];
    const float* s     = (const float*)d_in[2];
    const float* wq    = (const float*)d_in[3];
    const float* wk    = (const float*)d_in[4];
    const float* wv    = (const float*)d_in[5];
    const float* wqp   = (const float*)d_in[6];
    const float* wkp   = (const float*)d_in[7];
    const float* wvp   = (const float*)d_in[8];
    const float* gamma = (const float*)d_in[9];
    const float* wout  = (const float*)d_in[10];
    const float* wupd  = (const float*)d_in[11];
    const float* bupd  = (const float*)d_in[12];
    float* out = (float*)d_out;

    float *p_s_all, *p_k, *p_v, *p_kp, *p_vp, *p_q, *p_qp, *p_oc, *p_su;
    cudaGetSymbolAddress((void**)&p_s_all, g_s_all);
    cudaGetSymbolAddress((void**)&p_k, g_k);
    cudaGetSymbolAddress((void**)&p_v, g_v);
    cudaGetSymbolAddress((void**)&p_kp, g_kp);
    cudaGetSymbolAddress((void**)&p_vp, g_vp);
    cudaGetSymbolAddress((void**)&p_q, g_q);
    cudaGetSymbolAddress((void**)&p_qp, g_qp);
    cudaGetSymbolAddress((void**)&p_oc, g_oc);
    cudaGetSymbolAddress((void**)&p_su, g_su);

    // 1. pooling prep
    prep_s_kernel<<<(BB * TT * CSD + 255) / 256, 256>>>(s);
    prep_tr_kernel<<<(BB * TT * 12 + 255) / 256, 256>>>(trans, rots);

    // 2. projection GEMMs (all rows: k, v, kp, vp)
    int Mfull = BB * TT;  // 3076
    dim3 thr(256);
    sgemm_kernel<<<dim3((HC + 63) / 64, (Mfull + 63) / 64), thr>>>(p_s_all, wk, p_k, Mfull, HC, CSD);
    sgemm_kernel<<<dim3((HC + 63) / 64, (Mfull + 63) / 64), thr>>>(p_s_all, wv, p_v, Mfull, HC, CSD);
    sgemm_kernel<<<dim3((HPQ3 + 63) / 64, (Mfull + 63) / 64), thr>>>(p_s_all, wkp, p_kp, Mfull, HPQ3, CSD);
    sgemm_kernel<<<dim3((HPV3 + 63) / 64, (Mfull + 63) / 64), thr>>>(p_s_all, wvp, p_vp, Mfull, HPV3, CSD);

    // pooled-rows-only q / qp (per batch: contiguous row blocks)
    for (int b = 0; b < BB; b++) {
        const float* Aoff = p_s_all + (long)(b * TT + NPAD) * CSD;
        sgemm_kernel<<<dim3((HC + 63) / 64, (PROW + 63) / 64), thr>>>(
            Aoff, wq, p_q + (long)b * PROW * HC, PROW, HC, CSD);
        sgemm_kernel<<<dim3((HPQ3 + 63) / 64, (PROW + 63) / 64), thr>>>(
            Aoff, wqp, p_qp + (long)b * PROW * HPQ3, PROW, HPQ3, CSD);
    }

    // 3. point transforms to global frame
    transform_kv_kernel<<<(BB * TT * HH + 255) / 256, 256>>>();
    transform_q_kernel<<<(BB * PROW * HH + 255) / 256, 256>>>();

    // 4. attention (pooled queries only)
    attn_kernel<<<dim3(BB * HH, PROW / ATH), ATH>>>(gamma);

    // 5. epilogue
    build_oc_kernel<<<(BB * PROW * HH + 255) / 256, 256>>>();
    sgemm_kernel<<<dim3((CSD + 63) / 64, (BB * PROW + 63) / 64), thr>>>(
        p_oc, wout, p_su, BB * PROW, CSD, OCW);
    finalize_kernel<<<(BB * PROW + 255) / 256, 256>>>(wupd, bupd, out);
}

// round 2
// speedup vs baseline: 2.3609x; 2.3609x over previous
#include <cuda_runtime.h>
#include <math.h>

// Problem constants
#define BB 2
#define NN 1024
#define CSD 384
#define HH 12
#define CC 16
#define PQN 4
#define PVN 8
#define NPAD 1026        // N + 2*PAD
#define PROW 512         // num_pool
#define TT 1538          // NPAD + PROW
#define HC 192           // H*C
#define HPQ3 144         // H*PQ*3
#define HPV3 288         // H*PV*3
#define OCW 576          // HC + HPV3 + H*PV
#define ATTS 4           // split-KV factor
#define ACHUNK ((TT + ATTS - 1) / ATTS)   // 385

#define C1 0.176776695f       // w_l * (1/sqrt(C)) = sqrt(0.5)*0.25
#define WC_HALF 0.117851130f  // w_c/2 = sqrt(2/(9*PQ))/2

// Scratch (device globals; no allocation allowed)
__device__ float g_s_all[BB*TT*CSD];
__device__ float g_t_all[BB*TT*3];
__device__ float g_r_all[BB*TT*9];
__device__ float g_k  [BB*TT*HC];
__device__ float g_v  [BB*TT*HC];
__device__ float g_kp [BB*TT*HPQ3];   // local points -> global (in place)
__device__ float g_vp [BB*TT*HPV3];   // local points -> global (in place)
__device__ float g_sk [BB*TT*HH];
__device__ float g_q  [BB*PROW*HC];
__device__ float g_qp [BB*PROW*HPQ3]; // local -> global (in place)
__device__ float g_oc [BB*PROW*OCW];
__device__ float g_wfold[6*OCW];      // (wout @ wupd)^T : [6][OCW]

// split-KV partials, index p = ((b*PROW+i)*HH + h)*ATTS + s
#define NPART (BB*PROW*HH*ATTS)
__device__ float g_pm[NPART];
__device__ float g_pl[NPART];
__device__ float g_po[NPART*CC];
__device__ float g_pg[NPART*PVN*3];

__device__ __forceinline__ int clampsrc(int e) {
    int v = e - 1;
    return v < 0 ? 0 : (v > NN - 1 ? NN - 1 : v);
}

// ---------------------------------------------------------------------------
// Pooling prep
// ---------------------------------------------------------------------------
__global__ void prep_s_kernel(const float* __restrict__ s) {
    int idx = blockIdx.x * blockDim.x + threadIdx.x;
    if (idx >= BB * TT * CSD) return;
    int c = idx % CSD;
    int bt = idx / CSD;
    int t = bt % TT;
    int b = bt / TT;
    float val;
    if (t < NPAD) {
        val = s[(b * NN + clampsrc(t)) * CSD + c];
    } else {
        int p = t - NPAD;
        val = (s[(b * NN + clampsrc(2 * p    )) * CSD + c]
             + s[(b * NN + clampsrc(2 * p + 1)) * CSD + c]
             + s[(b * NN + clampsrc(2 * p + 2)) * CSD + c]) * (1.f / 3.f);
    }
    g_s_all[idx] = val;
}

__global__ void prep_tr_kernel(const float* __restrict__ trans,
                               const float* __restrict__ rots) {
    int idx = blockIdx.x * blockDim.x + threadIdx.x;
    if (idx >= BB * TT * 12) return;
    int d = idx % 12;
    int bt = idx / 12;
    int t = bt % TT;
    int b = bt / TT;
    if (d < 3) {
        float val;
        if (t < NPAD) {
            val = trans[(b * NN + clampsrc(t)) * 3 + d];
        } else {
            int p = t - NPAD;
            val = (trans[(b * NN + clampsrc(2 * p    )) * 3 + d]
                 + trans[(b * NN + clampsrc(2 * p + 1)) * 3 + d]
                 + trans[(b * NN + clampsrc(2 * p + 2)) * 3 + d]) * (1.f / 3.f);
        }
        g_t_all[(b * TT + t) * 3 + d] = val;
    } else {
        int r = d - 3;
        float val;
        if (t < NPAD) {
            val = rots[(b * NN + clampsrc(t)) * 9 + r];
        } else {
            int p = t - NPAD;
            val = (rots[(b * NN + clampsrc(2 * p    )) * 9 + r]
                 + rots[(b * NN + clampsrc(2 * p + 1)) * 9 + r]
                 + rots[(b * NN + clampsrc(2 * p + 2)) * 9 + r]) * (1.f / 3.f);
        }
        g_r_all[(b * TT + t) * 9 + r] = val;
    }
}

// ---------------------------------------------------------------------------
// Fused multi-task SGEMM: all 8 projection GEMMs in ONE launch.
// Tile 64x64, BK=16, 256 threads, 4x4/thread.
// ---------------------------------------------------------------------------
#define NTASK 8
struct GemmTask {
    const float* A;
    const float* B;
    float* C;
    int M, N, K, gx;
};
struct TaskPack {
    GemmTask t[NTASK];
    int ofs[NTASK + 1];
};

#define GBM 64
#define GBN 64
#define GBK 16
__global__ void mgemm_kernel(TaskPack P) {
    int bid = blockIdx.x;
    int ti = 0;
#pragma unroll
    for (int x = 0; x < NTASK - 1; x++)
        if (bid >= P.ofs[x + 1]) ti = x + 1;
    GemmTask tk = P.t[ti];
    int lb = bid - P.ofs[ti];
    int bx = lb % tk.gx, by = lb / tk.gx;

    __shared__ float As[GBK][GBM];
    __shared__ float Bs[GBK][GBN];
    int tid = threadIdx.x;
    int tx = tid % 16, ty = tid / 16;
    int row0 = by * GBM;
    int col0 = bx * GBN;
    const float* A = tk.A;
    const float* Bm = tk.B;
    int M = tk.M, Nn = tk.N, K = tk.K;

    float acc[4][4];
#pragma unroll
    for (int i = 0; i < 4; i++)
#pragma unroll
        for (int j = 0; j < 4; j++) acc[i][j] = 0.f;

    for (int k0 = 0; k0 < K; k0 += GBK) {
#pragma unroll
        for (int x = 0; x < (GBM * GBK) / 256; x++) {
            int li = tid + x * 256;
            int m = li / GBK, kk = li % GBK;
            int gm = row0 + m;
            As[kk][m] = (gm < M) ? A[(long)gm * K + k0 + kk] : 0.f;
        }
#pragma unroll
        for (int x = 0; x < (GBK * GBN) / 256; x++) {
            int li = tid + x * 256;
            int kk = li / GBN, n = li % GBN;
            int gn = col0 + n;
            Bs[kk][n] = (gn < Nn) ? Bm[(long)(k0 + kk) * Nn + gn] : 0.f;
        }
        __syncthreads();
#pragma unroll
        for (int kk = 0; kk < GBK; kk++) {
            float a[4], bvals[4];
#pragma unroll
            for (int i = 0; i < 4; i++) a[i] = As[kk][ty * 4 + i];
#pragma unroll
            for (int j = 0; j < 4; j++) bvals[j] = Bs[kk][tx * 4 + j];
#pragma unroll
            for (int i = 0; i < 4; i++)
#pragma unroll
                for (int j = 0; j < 4; j++) acc[i][j] += a[i] * bvals[j];
        }
        __syncthreads();
    }
#pragma unroll
    for (int i = 0; i < 4; i++) {
        int gm = row0 + ty * 4 + i;
        if (gm >= M) continue;
#pragma unroll
        for (int j = 0; j < 4; j++) {
            int gn = col0 + tx * 4 + j;
            if (gn < Nn) tk.C[(long)gm * Nn + gn] = acc[i][j];
        }
    }
}

// ---------------------------------------------------------------------------
// Fold wout @ wupd -> wfold[6][OCW]  (eliminates the big epilogue GEMM)
// ---------------------------------------------------------------------------
__global__ void fold_w_kernel(const float* __restrict__ wout,
                              const float* __restrict__ wupd) {
    int idx = blockIdx.x * blockDim.x + threadIdx.x;
    if (idx >= 6 * OCW) return;
    int j = idx / OCW;
    int k = idx % OCW;
    const float4* wr = reinterpret_cast<const float4*>(wout + (long)k * CSD);
    float acc = 0.f;
#pragma unroll 4
    for (int m4 = 0; m4 < CSD / 4; m4++) {
        float4 w = wr[m4];
        int m = m4 * 4;
        acc += w.x * wupd[(m    ) * 6 + j];
        acc += w.y * wupd[(m + 1) * 6 + j];
        acc += w.z * wupd[(m + 2) * 6 + j];
        acc += w.w * wupd[(m + 3) * 6 + j];
    }
    g_wfold[j * OCW + k] = acc;
}

// ---------------------------------------------------------------------------
// Point transforms to global frame (+ sk for keys)
// ---------------------------------------------------------------------------
__global__ void transform_kv_kernel() {
    int idx = blockIdx.x * blockDim.x + threadIdx.x;
    if (idx >= BB * TT * HH) return;
    int h = idx % HH;
    int rt = idx / HH;
    float R[9], tr[3];
#pragma unroll
    for (int r = 0; r < 9; r++) R[r] = g_r_all[rt * 9 + r];
#pragma unroll
    for (int r = 0; r < 3; r++) tr[r] = g_t_all[rt * 3 + r];

    float sk = 0.f;
    int kb = rt * HPQ3 + h * PQN * 3;
#pragma unroll
    for (int p = 0; p < PQN; p++) {
        float lx = g_kp[kb + p * 3 + 0];
        float ly = g_kp[kb + p * 3 + 1];
        float lz = g_kp[kb + p * 3 + 2];
        float gx = R[0] * lx + R[1] * ly + R[2] * lz + tr[0];
        float gy = R[3] * lx + R[4] * ly + R[5] * lz + tr[1];
        float gz = R[6] * lx + R[7] * ly + R[8] * lz + tr[2];
        g_kp[kb + p * 3 + 0] = gx;
        g_kp[kb + p * 3 + 1] = gy;
        g_kp[kb + p * 3 + 2] = gz;
        sk += gx * gx + gy * gy + gz * gz;
    }
    g_sk[rt * HH + h] = sk;

    int vb = rt * HPV3 + h * PVN * 3;
#pragma unroll
    for (int p = 0; p < PVN; p++) {
        float lx = g_vp[vb + p * 3 + 0];
        float ly = g_vp[vb + p * 3 + 1];
        float lz = g_vp[vb + p * 3 + 2];
        float gx = R[0] * lx + R[1] * ly + R[2] * lz + tr[0];
        float gy = R[3] * lx + R[4] * ly + R[5] * lz + tr[1];
        float gz = R[6] * lx + R[7] * ly + R[8] * lz + tr[2];
        g_vp[vb + p * 3 + 0] = gx;
        g_vp[vb + p * 3 + 1] = gy;
        g_vp[vb + p * 3 + 2] = gz;
    }
}

__global__ void transform_q_kernel() {
    int idx = blockIdx.x * blockDim.x + threadIdx.x;
    if (idx >= BB * PROW * HH) return;
    int h = idx % HH;
    int row = idx / HH;
    int b = row / PROW, i = row % PROW;
    int ridx = b * TT + NPAD + i;
    float R[9], tr[3];
#pragma unroll
    for (int r = 0; r < 9; r++) R[r] = g_r_all[ridx * 9 + r];
#pragma unroll
    for (int r = 0; r < 3; r++) tr[r] = g_t_all[ridx * 3 + r];
    int qb = row * HPQ3 + h * PQN * 3;
#pragma unroll
    for (int p = 0; p < PQN; p++) {
        float lx = g_qp[qb + p * 3 + 0];
        float ly = g_qp[qb + p * 3 + 1];
        float lz = g_qp[qb + p * 3 + 2];
        float gx = R[0] * lx + R[1] * ly + R[2] * lz + tr[0];
        float gy = R[3] * lx + R[4] * ly + R[5] * lz + tr[1];
        float gz = R[6] * lx + R[7] * ly + R[8] * lz + tr[2];
        g_qp[qb + p * 3 + 0] = gx;
        g_qp[qb + p * 3 + 1] = gy;
        g_qp[qb + p * 3 + 2] = gz;
    }
}

// ---------------------------------------------------------------------------
// Split-KV attention: grid (B*H, PROW/64, ATTS). One thread per query row,
// each split handles ~385 keys. Online softmax; partials to global.
// float4 smem reads throughout.
// ---------------------------------------------------------------------------
#define TJ 32
#define ATH 64
__global__ void attn_split_kernel(const float* __restrict__ gamma) {
    int bh = blockIdx.x;
    int b = bh / HH, h = bh % HH;
    int i = blockIdx.y * ATH + threadIdx.x;
    int sp = blockIdx.z;
    int tid = threadIdx.x;

    int j_begin = sp * ACHUNK;
    int j_end = j_begin + ACHUNK;
    if (j_end > TT) j_end = TT;

    __shared__ __align__(16) float k_s [TJ][CC];
    __shared__ __align__(16) float v_s [TJ][CC];
    __shared__ __align__(16) float kg_s[TJ][PQN * 3];
    __shared__ __align__(16) float vg_s[TJ][PVN * 3];
    __shared__ float sk_s[TJ];

    int qrow = b * PROW + i;
    float q[CC], qg[PQN * 3];
    {
        const float4* q4 = reinterpret_cast<const float4*>(g_q + (long)qrow * HC + h * CC);
#pragma unroll
        for (int c = 0; c < 4; c++) {
            float4 v = q4[c];
            q[c*4+0] = v.x; q[c*4+1] = v.y; q[c*4+2] = v.z; q[c*4+3] = v.w;
        }
        const float4* g4 = reinterpret_cast<const float4*>(g_qp + (long)qrow * HPQ3 + h * PQN * 3);
#pragma unroll
        for (int c = 0; c < 3; c++) {
            float4 v = g4[c];
            qg[c*4+0] = v.x; qg[c*4+1] = v.y; qg[c*4+2] = v.z; qg[c*4+3] = v.w;
        }
    }
    float sq = 0.f;
#pragma unroll
    for (int x = 0; x < PQN * 3; x++) sq += qg[x] * qg[x];

    float gm = gamma[h];
    float gcoef = logf(1.f + __expf(gm)) * WC_HALF;

    float mrun = -1e30f, lrun = 0.f;
    float ao[CC], ag[PVN * 3];
#pragma unroll
    for (int c = 0; c < CC; c++) ao[c] = 0.f;
#pragma unroll
    for (int x = 0; x < PVN * 3; x++) ag[x] = 0.f;

    for (int j0 = j_begin; j0 < j_end; j0 += TJ) {
        __syncthreads();
        // k: TJ*4 float4
        for (int x = tid; x < TJ * 4; x += ATH) {
            int j = x >> 2, c4 = x & 3;
            int jj = j0 + j;
            float4 v = (jj < TT)
                ? reinterpret_cast<const float4*>(g_k + ((long)(b * TT + jj) * HC + h * CC))[c4]
                : make_float4(0.f, 0.f, 0.f, 0.f);
            reinterpret_cast<float4*>(&k_s[j][0])[c4] = v;
        }
        for (int x = tid; x < TJ * 4; x += ATH) {
            int j = x >> 2, c4 = x & 3;
            int jj = j0 + j;
            float4 v = (jj < TT)
                ? reinterpret_cast<const float4*>(g_v + ((long)(b * TT + jj) * HC + h * CC))[c4]
                : make_float4(0.f, 0.f, 0.f, 0.f);
            reinterpret_cast<float4*>(&v_s[j][0])[c4] = v;
        }
        for (int x = tid; x < TJ * 3; x += ATH) {
            int j = x / 3, c4 = x % 3;
            int jj = j0 + j;
            float4 v = (jj < TT)
                ? reinterpret_cast<const float4*>(g_kp + ((long)(b * TT + jj) * HPQ3 + h * PQN * 3))[c4]
                : make_float4(0.f, 0.f, 0.f, 0.f);
            reinterpret_cast<float4*>(&kg_s[j][0])[c4] = v;
        }
        for (int x = tid; x < TJ * 6; x += ATH) {
            int j = x / 6, c4 = x % 6;
            int jj = j0 + j;
            float4 v = (jj < TT)
                ? reinterpret_cast<const float4*>(g_vp + ((long)(b * TT + jj) * HPV3 + h * PVN * 3))[c4]
                : make_float4(0.f, 0.f, 0.f, 0.f);
            reinterpret_cast<float4*>(&vg_s[j][0])[c4] = v;
        }
        for (int x = tid; x < TJ; x += ATH) {
            int jj = j0 + x;
            sk_s[x] = (jj < TT) ? g_sk[(long)(b * TT + jj) * HH + h] : 0.f;
        }
        __syncthreads();

        int nv = j_end - j0;
        if (nv > TJ) nv = TJ;

        float logit[TJ];
        float tmax = -1e30f;
#pragma unroll
        for (int jj = 0; jj < TJ; jj++) {
            float qk = 0.f;
            const float4* k4 = reinterpret_cast<const float4*>(&k_s[jj][0]);
#pragma unroll
            for (int c = 0; c < 4; c++) {
                float4 kv = k4[c];
                qk += q[c*4+0] * kv.x + q[c*4+1] * kv.y + q[c*4+2] * kv.z + q[c*4+3] * kv.w;
            }
            float dt = 0.f;
            const float4* g4 = reinterpret_cast<const float4*>(&kg_s[jj][0]);
#pragma unroll
            for (int c = 0; c < 3; c++) {
                float4 kv = g4[c];
                dt += qg[c*4+0] * kv.x + qg[c*4+1] * kv.y + qg[c*4+2] * kv.z + qg[c*4+3] * kv.w;
            }
            float d2 = sq + sk_s[jj] - 2.f * dt;
            float lg = C1 * qk - gcoef * d2;
            logit[jj] = (jj < nv) ? lg : -1e30f;
            tmax = fmaxf(tmax, logit[jj]);
        }
        float mn = fmaxf(mrun, tmax);
        float corr = __expf(mrun - mn);
        lrun *= corr;
#pragma unroll
        for (int c = 0; c < CC; c++) ao[c] *= corr;
#pragma unroll
        for (int x = 0; x < PVN * 3; x++) ag[x] *= corr;
#pragma unroll
        for (int jj = 0; jj < TJ; jj++) {
            float e = __expf(logit[jj] - mn);
            lrun += e;
            const float4* v4 = reinterpret_cast<const float4*>(&v_s[jj][0]);
#pragma unroll
            for (int c = 0; c < 4; c++) {
                float4 vv = v4[c];
                ao[c*4+0] += e * vv.x; ao[c*4+1] += e * vv.y;
                ao[c*4+2] += e * vv.z; ao[c*4+3] += e * vv.w;
            }
            const float4* g4 = reinterpret_cast<const float4*>(&vg_s[jj][0]);
#pragma unroll
            for (int c = 0; c < 6; c++) {
                float4 vv = g4[c];
                ag[c*4+0] += e * vv.x; ag[c*4+1] += e * vv.y;
                ag[c*4+2] += e * vv.z; ag[c*4+3] += e * vv.w;
            }
        }
        mrun = mn;
    }

    int p = (qrow * HH + h) * ATTS + sp;
    g_pm[p] = mrun;
    g_pl[p] = lrun;
#pragma unroll
    for (int c = 0; c < CC; c++) g_po[(long)p * CC + c] = ao[c];
#pragma unroll
    for (int x = 0; x < PVN * 3; x++) g_pg[(long)p * (PVN * 3) + x] = ag[x];
}

// ---------------------------------------------------------------------------
// Combine split partials + build oc rows [o | opl | norms] in one pass.
// One thread per (b,i,h).
// ---------------------------------------------------------------------------
__global__ void combine_oc_kernel() {
    int idx = blockIdx.x * blockDim.x + threadIdx.x;
    if (idx >= BB * PROW * HH) return;
    int h = idx % HH;
    int row = idx / HH;          // b*PROW+i
    int b = row / PROW, i = row % PROW;
    int p0 = idx * ATTS;

    float m = -1e30f;
#pragma unroll
    for (int s = 0; s < ATTS; s++) m = fmaxf(m, g_pm[p0 + s]);
    float L = 0.f;
    float o[CC], g[PVN * 3];
#pragma unroll
    for (int c = 0; c < CC; c++) o[c] = 0.f;
#pragma unroll
    for (int x = 0; x < PVN * 3; x++) g[x] = 0.f;
#pragma unroll
    for (int s = 0; s < ATTS; s++) {
        float w = __expf(g_pm[p0 + s] - m);
        L += g_pl[p0 + s] * w;
        const float* po = g_po + (long)(p0 + s) * CC;
        const float* pg = g_pg + (long)(p0 + s) * (PVN * 3);
#pragma unroll
        for (int c = 0; c < CC; c++) o[c] += w * po[c];
#pragma unroll
        for (int x = 0; x < PVN * 3; x++) g[x] += w * pg[x];
    }
    float inv = 1.f / L;
#pragma unroll
    for (int c = 0; c < CC; c++) o[c] *= inv;
#pragma unroll
    for (int x = 0; x < PVN * 3; x++) g[x] *= inv;

    int ridx = b * TT + NPAD + i;
    float R[9], tr[3];
#pragma unroll
    for (int r = 0; r < 9; r++) R[r] = g_r_all[ridx * 9 + r];
#pragma unroll
    for (int r = 0; r < 3; r++) tr[r] = g_t_all[ridx * 3 + r];

#pragma unroll
    for (int c = 0; c < CC; c++)
        g_oc[(long)row * OCW + h * CC + c] = o[c];

#pragma unroll
    for (int pp = 0; pp < PVN; pp++) {
        float gx = g[pp * 3 + 0] - tr[0];
        float gy = g[pp * 3 + 1] - tr[1];
        float gz = g[pp * 3 + 2] - tr[2];
        float lx = R[0] * gx + R[3] * gy + R[6] * gz;
        float ly = R[1] * gx + R[4] * gy + R[7] * gz;
        float lz = R[2] * gx + R[5] * gy + R[8] * gz;
        g_oc[(long)row * OCW + HC + h * PVN * 3 + pp * 3 + 0] = lx;
        g_oc[(long)row * OCW + HC + h * PVN * 3 + pp * 3 + 1] = ly;
        g_oc[(long)row * OCW + HC + h * PVN * 3 + pp * 3 + 2] = lz;
        g_oc[(long)row * OCW + HC + HPV3 + h * PVN + pp] =
            sqrtf(lx * lx + ly * ly + lz * lz + 1e-8f);
    }
}

// ---------------------------------------------------------------------------
// Finalize: warp per row. upd = oc @ wfold + bupd (576-dot, lanes split k),
// then quaternion rotation update and output writes.
// out layout: [t_new flat (B*PROW*3) | r_new flat (B*PROW*9)]
// ---------------------------------------------------------------------------
__global__ void finalize_kernel(const float* __restrict__ bupd,
                                float* __restrict__ out) {
    int gw = (blockIdx.x * blockDim.x + threadIdx.x) >> 5;
    int lane = threadIdx.x & 31;
    if (gw >= BB * PROW) return;
    int row = gw;
    int b = row / PROW, i = row % PROW;
    int ridx = b * TT + NPAD + i;

    float acc[6] = {0.f, 0.f, 0.f, 0.f, 0.f, 0.f};
    const float* ocr = g_oc + (long)row * OCW;
    for (int k = lane; k < OCW; k += 32) {
        float v = ocr[k];
#pragma unroll
        for (int j = 0; j < 6; j++) acc[j] += v * g_wfold[j * OCW + k];
    }
#pragma unroll
    for (int off = 16; off > 0; off >>= 1) {
#pragma unroll
        for (int j = 0; j < 6; j++)
            acc[j] += __shfl_down_sync(0xffffffffu, acc[j], off);
    }
    if (lane != 0) return;

    float u[6];
#pragma unroll
    for (int j = 0; j < 6; j++) u[j] = acc[j] + bupd[j];

    float bq = u[0], cq = u[1], dq = u[2];
    float ninv = rsqrtf(1.f + bq * bq + cq * cq + dq * dq);
    float w = ninv, x = bq * ninv, y = cq * ninv, z = dq * ninv;
    float Ru[9];
    Ru[0] = 1.f - 2.f * (y * y + z * z); Ru[1] = 2.f * (x * y - w * z); Ru[2] = 2.f * (x * z + w * y);
    Ru[3] = 2.f * (x * y + w * z); Ru[4] = 1.f - 2.f * (x * x + z * z); Ru[5] = 2.f * (y * z - w * x);
    Ru[6] = 2.f * (x * z - w * y); Ru[7] = 2.f * (y * z + w * x); Ru[8] = 1.f - 2.f * (x * x + y * y);

    float R[9];
#pragma unroll
    for (int r = 0; r < 9; r++) R[r] = g_r_all[ridx * 9 + r];

    float Rn[9];
#pragma unroll
    for (int r = 0; r < 3; r++)
#pragma unroll
        for (int c = 0; c < 3; c++) {
            float a = 0.f;
#pragma unroll
            for (int k = 0; k < 3; k++) a += R[r * 3 + k] * Ru[k * 3 + c];
            Rn[r * 3 + c] = a;
        }

    out[row * 3 + 0] = R[0] * u[3] + R[1] * u[4] + R[2] * u[5] + g_t_all[ridx * 3 + 0];
    out[row * 3 + 1] = R[3] * u[3] + R[4] * u[4] + R[5] * u[5] + g_t_all[ridx * 3 + 1];
    out[row * 3 + 2] = R[6] * u[3] + R[7] * u[4] + R[8] * u[5] + g_t_all[ridx * 3 + 2];
    float* rout = out + BB * PROW * 3;
#pragma unroll
    for (int r = 0; r < 9; r++) rout[row * 9 + r] = Rn[r];
}

// ---------------------------------------------------------------------------
extern "C" void kernel_launch(void* const* d_in, const int* in_sizes, int n_in,
                              void* d_out, int out_size) {
    const float* trans = (const float*)d_in[0];
    const float* rots  = (const float*)d_in[1];
    const float* s     = (const float*)d_in[2];
    const float* wq    = (const float*)d_in[3];
    const float* wk    = (const float*)d_in[4];
    const float* wv    = (const float*)d_in[5];
    const float* wqp   = (const float*)d_in[6];
    const float* wkp   = (const float*)d_in[7];
    const float* wvp   = (const float*)d_in[8];
    const float* gamma = (const float*)d_in[9];
    const float* wout  = (const float*)d_in[10];
    const float* wupd  = (const float*)d_in[11];
    const float* bupd  = (const float*)d_in[12];
    float* out = (float*)d_out;

    float *p_s_all, *p_k, *p_v, *p_kp, *p_vp, *p_q, *p_qp;
    cudaGetSymbolAddress((void**)&p_s_all, g_s_all);
    cudaGetSymbolAddress((void**)&p_k, g_k);
    cudaGetSymbolAddress((void**)&p_v, g_v);
    cudaGetSymbolAddress((void**)&p_kp, g_kp);
    cudaGetSymbolAddress((void**)&p_vp, g_vp);
    cudaGetSymbolAddress((void**)&p_q, g_q);
    cudaGetSymbolAddress((void**)&p_qp, g_qp);

    // 1. pooling prep
    prep_s_kernel<<<(BB * TT * CSD + 255) / 256, 256>>>(s);
    prep_tr_kernel<<<(BB * TT * 12 + 255) / 256, 256>>>(trans, rots);

    // 2. ALL projection GEMMs fused into one launch
    TaskPack P;
    int Mfull = BB * TT;
    auto setTask = [&](int ti, const float* A, const float* B, float* C,
                       int M, int N, int K) {
        P.t[ti].A = A; P.t[ti].B = B; P.t[ti].C = C;
        P.t[ti].M = M; P.t[ti].N = N; P.t[ti].K = K;
        P.t[ti].gx = (N + GBN - 1) / GBN;
    };
    setTask(0, p_s_all, wk,  p_k,  Mfull, HC,   CSD);
    setTask(1, p_s_all, wv,  p_v,  Mfull, HC,   CSD);
    setTask(2, p_s_all, wkp, p_kp, Mfull, HPQ3, CSD);
    setTask(3, p_s_all, wvp, p_vp, Mfull, HPV3, CSD);
    setTask(4, p_s_all + (long)NPAD * CSD,            wq,  p_q,                       PROW, HC,   CSD);
    setTask(5, p_s_all + (long)(TT + NPAD) * CSD,     wq,  p_q + (long)PROW * HC,     PROW, HC,   CSD);
    setTask(6, p_s_all + (long)NPAD * CSD,            wqp, p_qp,                      PROW, HPQ3, CSD);
    setTask(7, p_s_all + (long)(TT + NPAD) * CSD,     wqp, p_qp + (long)PROW * HPQ3,  PROW, HPQ3, CSD);
    P.ofs[0] = 0;
    for (int ti = 0; ti < NTASK; ti++) {
        int gy = (P.t[ti].M + GBM - 1) / GBM;
        P.ofs[ti + 1] = P.ofs[ti] + P.t[ti].gx * gy;
    }
    mgemm_kernel<<<P.ofs[NTASK], 256>>>(P);

    // 3. weight fold (independent of everything above except wout/wupd)
    fold_w_kernel<<<(6 * OCW + 255) / 256, 256>>>(wout, wupd);

    // 4. point transforms
    transform_kv_kernel<<<(BB * TT * HH + 255) / 256, 256>>>();
    transform_q_kernel<<<(BB * PROW * HH + 255) / 256, 256>>>();

    // 5. split-KV attention
    attn_split_kernel<<<dim3(BB * HH, PROW / ATH, ATTS), ATH>>>(gamma);

    // 6. combine + build oc
    combine_oc_kernel<<<(BB * PROW * HH + 255) / 256, 256>>>();

    // 7. finalize (warp per row)
    finalize_kernel<<<(BB * PROW * 32 + 255) / 256, 256>>>(bupd, out);
}